// round 2
// baseline (speedup 1.0000x reference)
#include <cuda_runtime.h>

// ---------------- problem constants ----------------
#define NB 32
#define NT 30
#define NC 128
#define HW 14
#define NPIX 196          // 14*14
#define PPIX 256          // 16*16 padded
#define CN (NC*NPIX)      // 25088 floats per (batch, 128ch) tensor
#define CONV_DIM (128*128*9)
#define OCG 8             // out channels per block
#define NOCG 16           // 128/OCG
#define CHUNK 16          // input channels per smem chunk

// token tables (compile-time constants of the problem definition)
__constant__ int c_kind[44] = {
  0,0,0,0, 1, 3,3,3,3,3,
  2,2,2,2,2,2,2,2,2,2,2,2,2,2,2,2,   // 10..25
  3,3,3,                              // 26..28
  2,2,2,2,2,2,2,2,2,2,2,2,2,         // 29..41
  3, 2};                             // 42, 43
__constant__ int c_uidx[44] = {
  0,0,0,0, 0, 0,0,0,0,0,
  1,2,3,4,5,6,7,8,9,10,11,12,13,14,15,16,
  0,0,0,
  17,18,19,20,21,22,23,24,25,26,27,28,29,
  0, 30};
__constant__ int c_bidx[44] = {
  0,0,0,0, 0, 0,1,2,3,4,
  0,0,0,0,0,0,0,0,0,0,0,0,0,0,0,0,
  5,6,7,
  0,0,0,0,0,0,0,0,0,0,0,0,0,
  8, 0};

// ---------------- device scratch ----------------
__device__ float g_h1[NB*CN];
__device__ float g_feat[NB*CN];
__device__ float g_out[NB*CN];
__device__ float g_saved[NB*CN];
__device__ float g_tmp1[NB*CN];
__device__ float g_tmp2[NB*CN];
__device__ float g_cls[NB*512*NPIX];
__device__ float g_pool[NB*512*49];
__device__ float g_fc1p[8*NB*1024];

// ---------------- generic 3x3 conv accumulator ----------------
// Block: 256 threads; thread tid<196 owns output position tid.
// Computes OCG out channels for out-channel group `ocg`.
// in1 != nullptr -> channels >=128 come from in1 (concat for binary module).
__device__ __forceinline__ void conv3x3_acc(
    const float* __restrict__ in0, const float* __restrict__ in1,
    int in_ch, const float* __restrict__ w, int ocg, float acc[OCG])
{
    __shared__ float s_in[CHUNK][PPIX];       // 16 KB
    __shared__ float s_w[CHUNK][9][OCG];      // 4.6 KB
    const int tid = threadIdx.x;
    const int py = tid / 14, px = tid - 14*(tid/14);
#pragma unroll
    for (int i = 0; i < OCG; ++i) acc[i] = 0.f;
    const int nchunk = in_ch >> 4;
    const int wocstride = in_ch * 9;
    const int ocbase = ocg * OCG;
    for (int ch = 0; ch < nchunk; ++ch) {
        const int ci0 = ch * CHUNK;
        // load 16 input channels, zero-padded 16x16
        for (int idx = tid; idx < CHUNK * PPIX; idx += 256) {
            int ci  = idx >> 8;
            int pix = idx & 255;
            int iy  = (pix >> 4) - 1;
            int ix  = (pix & 15) - 1;
            float v = 0.f;
            if (iy >= 0 && iy < HW && ix >= 0 && ix < HW) {
                int cg = ci0 + ci;
                const float* src = (in1 != nullptr && cg >= NC)
                                   ? (in1 + (cg - NC) * NPIX)
                                   : (in0 + cg * NPIX);
                v = src[iy * HW + ix];
            }
            s_in[ci][pix] = v;
        }
        // load weights for this chunk: OCG oc x CHUNK ci x 9
        for (int idx = tid; idx < OCG * CHUNK * 9; idx += 256) {
            int oc = idx / (CHUNK * 9);
            int r  = idx - oc * (CHUNK * 9);
            int ci = r / 9;
            int t  = r - ci * 9;
            s_w[ci][t][oc] = w[(size_t)(ocbase + oc) * wocstride + (ci0 + ci) * 9 + t];
        }
        __syncthreads();
        if (tid < NPIX) {
#pragma unroll 2
            for (int ci = 0; ci < CHUNK; ++ci) {
                const float* row = &s_in[ci][py * 16 + px];
                float vv[9];
                vv[0] = row[0];  vv[1] = row[1];  vv[2] = row[2];
                vv[3] = row[16]; vv[4] = row[17]; vv[5] = row[18];
                vv[6] = row[32]; vv[7] = row[33]; vv[8] = row[34];
#pragma unroll
                for (int t = 0; t < 9; ++t) {
#pragma unroll
                    for (int oc = 0; oc < OCG; ++oc)
                        acc[oc] += vv[t] * s_w[ci][t][oc];
                }
            }
        }
        __syncthreads();
    }
}

// ---------------- stem ----------------
__global__ void k_stem1(const float* __restrict__ feats,
                        const float* __restrict__ w,
                        const float* __restrict__ bias)
{
    int b = blockIdx.y, ocg = blockIdx.x;
    float acc[OCG];
    conv3x3_acc(feats + (size_t)b * 1024 * NPIX, nullptr, 1024, w, ocg, acc);
    int tid = threadIdx.x;
    if (tid < NPIX) {
#pragma unroll
        for (int oc = 0; oc < OCG; ++oc) {
            float r = acc[oc] + bias[ocg * OCG + oc];
            g_h1[b * CN + (ocg * OCG + oc) * NPIX + tid] = r > 0.f ? r : 0.f;
        }
    }
}

__global__ void k_stem2(const float* __restrict__ w,
                        const float* __restrict__ bias)
{
    int b = blockIdx.y, ocg = blockIdx.x;
    float acc[OCG];
    conv3x3_acc(g_h1 + b * CN, nullptr, NC, w, ocg, acc);
    int tid = threadIdx.x;
    if (tid < NPIX) {
#pragma unroll
        for (int oc = 0; oc < OCG; ++oc) {
            float r = acc[oc] + bias[ocg * OCG + oc];
            r = r > 0.f ? r : 0.f;
            int idx = b * CN + (ocg * OCG + oc) * NPIX + tid;
            g_feat[idx]  = r;
            g_out[idx]   = r;     // scan carry init: out = feat
            g_saved[idx] = 0.f;   // scan carry init: saved = 0
        }
    }
}

// ---------------- scan stages ----------------
__global__ void k_stage1(const int* __restrict__ programs,
                         const float* __restrict__ mem_u,
                         const float* __restrict__ mem_b, int step)
{
    int b = blockIdx.y, ocg = blockIdx.x;
    int tok = programs[b * NT + (NT - 1 - step)];
    int kind = c_kind[tok];
    if (kind == 0) return;
    const float* inA; const float* inB = nullptr; const float* w; int in_ch = NC;
    if (kind == 3) {
        inA = g_out + b * CN; inB = g_saved + b * CN;
        w = mem_b + (size_t)c_bidx[tok] * 4 * CONV_DIM;  // bw1: [128][256][9]
        in_ch = 2 * NC;
    } else {
        inA = (kind == 1 ? g_feat : g_out) + b * CN;
        w = mem_u + (size_t)c_uidx[tok] * 2 * CONV_DIM;  // w1
    }
    float acc[OCG];
    conv3x3_acc(inA, inB, in_ch, w, ocg, acc);
    int tid = threadIdx.x;
    if (tid < NPIX) {
#pragma unroll
        for (int oc = 0; oc < OCG; ++oc) {
            float r = acc[oc];
            g_tmp1[b * CN + (ocg * OCG + oc) * NPIX + tid] = r > 0.f ? r : 0.f;
        }
    }
    // scene token: new_saved = old out (this block copies its channel slice)
    if (kind == 1) {
        int base = b * CN + ocg * OCG * NPIX;
        for (int i = threadIdx.x; i < OCG * NPIX; i += 256)
            g_saved[base + i] = g_out[base + i];
    }
}

__global__ void k_stage2(const int* __restrict__ programs,
                         const float* __restrict__ mem_u,
                         const float* __restrict__ mem_b, int step)
{
    int b = blockIdx.y, ocg = blockIdx.x;
    int tok = programs[b * NT + (NT - 1 - step)];
    int kind = c_kind[tok];
    if (kind == 0) return;
    const float* w; float* out;
    if (kind == 3) {
        w = mem_b + (size_t)c_bidx[tok] * 4 * CONV_DIM + 2 * CONV_DIM;  // bw2
        out = g_tmp2;
    } else {
        w = mem_u + (size_t)c_uidx[tok] * 2 * CONV_DIM + CONV_DIM;      // w2
        out = g_out;  // unary result is the new out
    }
    float acc[OCG];
    conv3x3_acc(g_tmp1 + b * CN, nullptr, NC, w, ocg, acc);
    int tid = threadIdx.x;
    if (tid < NPIX) {
#pragma unroll
        for (int oc = 0; oc < OCG; ++oc) {
            float r = acc[oc];
            out[b * CN + (ocg * OCG + oc) * NPIX + tid] = r > 0.f ? r : 0.f;
        }
    }
}

__global__ void k_stage3(const int* __restrict__ programs,
                         const float* __restrict__ mem_b, int step)
{
    int b = blockIdx.y, ocg = blockIdx.x;
    int tok = programs[b * NT + (NT - 1 - step)];
    if (c_kind[tok] != 3) return;
    const float* w = mem_b + (size_t)c_bidx[tok] * 4 * CONV_DIM + 3 * CONV_DIM;  // bw3
    float acc[OCG];
    conv3x3_acc(g_tmp2 + b * CN, nullptr, NC, w, ocg, acc);
    int tid = threadIdx.x;
    if (tid < NPIX) {
#pragma unroll
        for (int oc = 0; oc < OCG; ++oc) {
            float r = acc[oc];
            g_out[b * CN + (ocg * OCG + oc) * NPIX + tid] = r > 0.f ? r : 0.f;
        }
    }
}

// ---------------- classifier head ----------------
// conv1x1 128->512 + bias + relu. Block = (ocg of 16, batch), 256 threads.
__global__ void k_cls(const float* __restrict__ w, const float* __restrict__ bias)
{
    __shared__ float s_in[32][NPIX];
    __shared__ float s_w[32][16];
    int b = blockIdx.y, ocg = blockIdx.x;   // ocg 0..31 (16 oc each)
    int tid = threadIdx.x;
    float acc[16];
#pragma unroll
    for (int i = 0; i < 16; ++i) acc[i] = 0.f;
    for (int ch = 0; ch < 4; ++ch) {
        for (int idx = tid; idx < 32 * NPIX; idx += 256) {
            int ci = idx / NPIX, p = idx - ci * NPIX;
            s_in[ci][p] = g_out[b * CN + (ch * 32 + ci) * NPIX + p];
        }
        for (int idx = tid; idx < 32 * 16; idx += 256) {
            int ci = idx >> 4, oc = idx & 15;
            s_w[ci][oc] = w[(ocg * 16 + oc) * NC + ch * 32 + ci];
        }
        __syncthreads();
        if (tid < NPIX) {
#pragma unroll 4
            for (int ci = 0; ci < 32; ++ci) {
                float v = s_in[ci][tid];
#pragma unroll
                for (int oc = 0; oc < 16; ++oc)
                    acc[oc] += v * s_w[ci][oc];
            }
        }
        __syncthreads();
    }
    if (tid < NPIX) {
#pragma unroll
        for (int oc = 0; oc < 16; ++oc) {
            float r = acc[oc] + bias[ocg * 16 + oc];
            g_cls[((size_t)b * 512 + ocg * 16 + oc) * NPIX + tid] = r > 0.f ? r : 0.f;
        }
    }
}

__global__ void k_pool()
{
    int idx = blockIdx.x * blockDim.x + threadIdx.x;
    if (idx >= NB * 512 * 49) return;
    int px = idx % 7;
    int r = idx / 7;
    int py = r % 7; r /= 7;
    int c = r % 512;
    int b = r / 512;
    const float* src = g_cls + (((size_t)b * 512 + c) * NPIX) + (2 * py) * HW + 2 * px;
    float m = fmaxf(fmaxf(src[0], src[1]), fmaxf(src[HW], src[HW + 1]));
    g_pool[idx] = m;
}

// fc1: (32,1024) = pool(32,25088) @ W^T, K-split by 8 into partial buffers.
__global__ void k_fc1(const float* __restrict__ w)
{
    __shared__ float s_x[32][64];
    __shared__ float s_w[64][65];
    int oc0 = blockIdx.x * 64;           // 16 groups
    int k0  = blockIdx.y * 3136;         // 8 K-slices
    int tid = threadIdx.x;
    int oc_t = tid & 63;
    int bq   = tid >> 6;                 // 0..3, each owns 8 batches
    float acc[8];
#pragma unroll
    for (int j = 0; j < 8; ++j) acc[j] = 0.f;
    for (int ch = 0; ch < 49; ++ch) {
        int kk0 = k0 + ch * 64;
        for (int idx = tid; idx < 2048; idx += 256) {
            int b = idx >> 6, kk = idx & 63;
            s_x[b][kk] = g_pool[b * 25088 + kk0 + kk];
        }
        for (int idx = tid; idx < 4096; idx += 256) {
            int oc = idx >> 6, kk = idx & 63;
            s_w[oc][kk] = w[(size_t)(oc0 + oc) * 25088 + kk0 + kk];
        }
        __syncthreads();
#pragma unroll 4
        for (int kk = 0; kk < 64; ++kk) {
            float wv = s_w[oc_t][kk];
#pragma unroll
            for (int j = 0; j < 8; ++j)
                acc[j] += wv * s_x[bq * 8 + j][kk];
        }
        __syncthreads();
    }
#pragma unroll
    for (int j = 0; j < 8; ++j) {
        int b = bq * 8 + j;
        g_fc1p[(size_t)blockIdx.y * NB * 1024 + b * 1024 + oc0 + oc_t] = acc[j];
    }
}

// fc2: reduce 8 K-slice partials + fc1 bias + relu, then 1024->32 + bias.
__global__ void k_fc2(const float* __restrict__ w2, const float* __restrict__ b2,
                      const float* __restrict__ fc1_b, float* __restrict__ out)
{
    __shared__ float s_x[1024];
    __shared__ float s_red[8][32];
    int b = blockIdx.x, tid = threadIdx.x;
    for (int j = tid; j < 1024; j += 256) {
        float s = fc1_b[j];
        for (int ks = 0; ks < 8; ++ks)
            s += g_fc1p[(size_t)ks * NB * 1024 + b * 1024 + j];
        s_x[j] = s > 0.f ? s : 0.f;
    }
    __syncthreads();
    int a = tid & 31, part = tid >> 5;
    float acc = 0.f;
    int j0 = part * 128;
    for (int j = j0; j < j0 + 128; ++j)
        acc += s_x[j] * w2[a * 1024 + j];
    s_red[part][a] = acc;
    __syncthreads();
    if (tid < 32) {
        float s = b2[tid];
#pragma unroll
        for (int p = 0; p < 8; ++p) s += s_red[p][tid];
        out[b * 32 + tid] = s;
    }
}

// ---------------- launch ----------------
extern "C" void kernel_launch(void* const* d_in, const int* in_sizes, int n_in,
                              void* d_out, int out_size)
{
    const float* feats    = (const float*)d_in[0];
    const int*   programs = (const int*)  d_in[1];
    const float* stem_w1  = (const float*)d_in[2];
    const float* stem_b1  = (const float*)d_in[3];
    const float* stem_w2  = (const float*)d_in[4];
    const float* stem_b2  = (const float*)d_in[5];
    const float* mem_u    = (const float*)d_in[6];
    const float* mem_b    = (const float*)d_in[7];
    const float* cls_w    = (const float*)d_in[8];
    const float* cls_b    = (const float*)d_in[9];
    const float* fc1_w    = (const float*)d_in[10];
    const float* fc1_b    = (const float*)d_in[11];
    const float* fc2_w    = (const float*)d_in[12];
    const float* fc2_b    = (const float*)d_in[13];
    float* out = (float*)d_out;

    dim3 gc(NOCG, NB);
    k_stem1<<<gc, 256>>>(feats, stem_w1, stem_b1);
    k_stem2<<<gc, 256>>>(stem_w2, stem_b2);
    for (int s = 0; s < NT; ++s) {
        k_stage1<<<gc, 256>>>(programs, mem_u, mem_b, s);
        k_stage2<<<gc, 256>>>(programs, mem_u, mem_b, s);
        k_stage3<<<gc, 256>>>(programs, mem_b, s);
    }
    k_cls<<<dim3(32, NB), 256>>>(cls_w, cls_b);
    k_pool<<<(NB * 512 * 49 + 255) / 256, 256>>>();
    k_fc1<<<dim3(16, 8), 256>>>(fc1_w);
    k_fc2<<<NB, 256>>>(fc2_w, fc2_b, fc1_b, out);
}

// round 3
// speedup vs baseline: 1.2024x; 1.2024x over previous
#include <cuda_runtime.h>

// ---------------- problem constants ----------------
#define NB 32
#define NT 30
#define NC 128
#define HW 14
#define NPIX 196
#define PCH 256            // padded 16x16 per channel
#define PCN (NC*PCH)       // 32768 floats per (b, 128ch) padded tensor
#define CONV_DIM (128*128*9)
#define CHUNK 8            // input channels per smem chunk

// token tables
__constant__ int c_kind[44] = {
  0,0,0,0, 1, 3,3,3,3,3,
  2,2,2,2,2,2,2,2,2,2,2,2,2,2,2,2,
  3,3,3,
  2,2,2,2,2,2,2,2,2,2,2,2,2,
  3, 2};
__constant__ int c_uidx[44] = {
  0,0,0,0, 0, 0,0,0,0,0,
  1,2,3,4,5,6,7,8,9,10,11,12,13,14,15,16,
  0,0,0,
  17,18,19,20,21,22,23,24,25,26,27,28,29,
  0, 30};
__constant__ int c_bidx[44] = {
  0,0,0,0, 0, 0,1,2,3,4,
  0,0,0,0,0,0,0,0,0,0,0,0,0,0,0,0,
  5,6,7,
  0,0,0,0,0,0,0,0,0,0,0,0,0,
  8, 0};

// ---------------- device scratch (padded layouts) ----------------
__device__ float g_featsP[NB*1024*PCH];  // padded stem input
__device__ float g_h1[NB*PCN];
__device__ float g_feat[NB*PCN];
__device__ float g_out[NB*PCN];
__device__ float g_saved[NB*PCN];
__device__ float g_tmp1[NB*PCN];
__device__ float g_tmp2[NB*PCN];
__device__ float g_cls[NB*512*NPIX];
__device__ float g_pool[NB*512*49];
__device__ float g_fc1p[8*NB*1024];

// ---------------- cp.async helpers ----------------
__device__ __forceinline__ void cp_async16(void* smem_dst, const void* gsrc) {
    unsigned s = (unsigned)__cvta_generic_to_shared(smem_dst);
    asm volatile("cp.async.cg.shared.global [%0], [%1], 16;\n" :: "r"(s), "l"(gsrc));
}
__device__ __forceinline__ void cp_commit() { asm volatile("cp.async.commit_group;\n"); }
__device__ __forceinline__ void cp_wait0()  { asm volatile("cp.async.wait_group 0;\n"); }

// ---------------- conv core ----------------
// Block: 224 threads. tid -> ocs = tid/56 (0..3), qid = tid%56 (quad: qy=qid>>3, qx=qid&7).
// Thread computes 2x2 output pixels (y=2qy+r, x=2qx+c) for 8 out channels
// (oc = ocg*32 + ocs*8 + k). qx==7 quads are padding (x=14,15), never stored.
// Inputs are padded [ch][16x16] with zero borders: output (y,x) reads padded
// rows y..y+2, cols x..x+2 directly.
__device__ __forceinline__ void conv_core(
    const float* __restrict__ inA, const float* __restrict__ inB,
    int nchunk, const float* __restrict__ w, int wstride,
    int ocg, float acc[2][2][8])
{
    __shared__ __align__(16) float s_in[2][CHUNK*PCH + 72];   // +72 pad for quad over-read
    __shared__ __align__(16) float s_w[2][CHUNK*9][36];       // [ci*9+t][oc], pad 36
    const int tid = threadIdx.x;
    const int ocs = tid / 56;
    const int qid = tid - ocs*56;
    const int qy = qid >> 3, qx = qid & 7;
    const int p0 = qy*32 + qx*2;
    const int ocbase = ocg*32;
    const int WCNT = 32*CHUNK*9;   // 2304 weight floats per chunk

#pragma unroll
    for (int r=0;r<2;++r)
#pragma unroll
    for (int c=0;c<2;++c)
#pragma unroll
    for (int k=0;k<8;++k) acc[r][c][k]=0.f;

    float wreg[11];

    // ---- prologue: chunk 0 ----
    for (int idx=tid; idx<CHUNK*PCH/4; idx+=224)
        cp_async16(&s_in[0][idx*4], (const float*)inA + idx*4);
    cp_commit();
    {
        int n=0;
        for (int idx=tid; idx<WCNT; idx+=224) {
            int oc = idx/(CHUNK*9), r = idx - oc*(CHUNK*9);
            wreg[n++] = w[(size_t)(ocbase+oc)*wstride + r];
        }
        cp_wait0(); __syncthreads();
        n=0;
        for (int idx=tid; idx<WCNT; idx+=224) {
            int oc = idx/(CHUNK*9), r = idx - oc*(CHUNK*9);
            s_w[0][r][oc] = wreg[n++];
        }
        __syncthreads();
    }

    for (int nc=0; nc<nchunk; ++nc) {
        const int nb = nc & 1;
        // prefetch chunk nc+1
        int n=0;
        if (nc+1 < nchunk) {
            const int cg0 = (nc+1)*CHUNK;
            const float* src = (inB != nullptr && cg0 >= NC) ? inB + (cg0-NC)*PCH
                                                             : inA + cg0*PCH;
            for (int idx=tid; idx<CHUNK*PCH/4; idx+=224)
                cp_async16(&s_in[nb^1][idx*4], src + idx*4);
            cp_commit();
            const int wbase = cg0*9;
            for (int idx=tid; idx<WCNT; idx+=224) {
                int oc = idx/(CHUNK*9), r = idx - oc*(CHUNK*9);
                wreg[n++] = w[(size_t)(ocbase+oc)*wstride + wbase + r];
            }
        }
        // compute chunk nc
        const float* sf = s_in[nb];
#pragma unroll 2
        for (int ci=0; ci<CHUNK; ++ci) {
            const float* bp = sf + ci*PCH + p0;
            float p[4][4];
#pragma unroll
            for (int rr=0; rr<4; ++rr) {
                float2 a = *(const float2*)(bp + rr*16);
                float2 b = *(const float2*)(bp + rr*16 + 2);
                p[rr][0]=a.x; p[rr][1]=a.y; p[rr][2]=b.x; p[rr][3]=b.y;
            }
#pragma unroll
            for (int t=0; t<9; ++t) {
                const float* wp = &s_w[nb][ci*9+t][ocs*8];
                float4 w0 = *(const float4*)wp;
                float4 w1 = *(const float4*)(wp+4);
                float wv[8] = {w0.x,w0.y,w0.z,w0.w,w1.x,w1.y,w1.z,w1.w};
                const int ty=t/3, tx=t-3*(t/3);
#pragma unroll
                for (int r=0;r<2;++r)
#pragma unroll
                for (int c=0;c<2;++c) {
                    float pv = p[r+ty][c+tx];
#pragma unroll
                    for (int k=0;k<8;++k) acc[r][c][k] += pv*wv[k];
                }
            }
        }
        cp_wait0();
        __syncthreads();                // all compute on s_w[nb^1]'s previous tenant done
        if (nc+1 < nchunk) {
            n=0;
            for (int idx=tid; idx<WCNT; idx+=224) {
                int oc = idx/(CHUNK*9), r = idx - oc*(CHUNK*9);
                s_w[nb^1][r][oc] = wreg[n++];
            }
        }
        __syncthreads();
    }
}

// epilogue: bias(optional) + relu, store to padded dst (and optional dst2)
__device__ __forceinline__ void store_out(
    float* __restrict__ dst, float* __restrict__ dst2,
    const float* __restrict__ bias, int ocg, float acc[2][2][8])
{
    const int tid = threadIdx.x;
    const int ocs = tid / 56;
    const int qid = tid - ocs*56;
    const int qy = qid >> 3, qx = qid & 7;
    if (qx == 7) return;
#pragma unroll
    for (int r=0;r<2;++r)
#pragma unroll
    for (int c=0;c<2;++c) {
        const int y = 2*qy+r, x = 2*qx+c;
        const int pi = (y+1)*16 + (x+1);
#pragma unroll
        for (int k=0;k<8;++k) {
            const int oc = ocg*32 + ocs*8 + k;
            float v = acc[r][c][k];
            if (bias) v += bias[oc];
            v = v > 0.f ? v : 0.f;
            dst[oc*PCH + pi] = v;
            if (dst2) dst2[oc*PCH + pi] = v;
        }
    }
}

// ---------------- init kernels ----------------
__global__ void k_clear()
{
    size_t i = (size_t)blockIdx.x*blockDim.x + threadIdx.x;
    const size_t n = (size_t)NB*PCN;   // per buffer
    for (size_t j = i; j < n; j += (size_t)gridDim.x*blockDim.x) {
        g_h1[j]=0.f; g_feat[j]=0.f; g_out[j]=0.f;
        g_saved[j]=0.f; g_tmp1[j]=0.f; g_tmp2[j]=0.f;
    }
}
__global__ void k_pad(const float* __restrict__ feats)
{
    size_t i = (size_t)blockIdx.x*blockDim.x + threadIdx.x;
    const size_t n = (size_t)NB*1024*PCH;
    for (size_t j = i; j < n; j += (size_t)gridDim.x*blockDim.x) {
        int px = j & 15, py = (j >> 4) & 15;
        size_t bc = j >> 8;                  // b*1024 + c
        float v = 0.f;
        if (px >= 1 && px <= 14 && py >= 1 && py <= 14)
            v = feats[bc*NPIX + (py-1)*14 + (px-1)];
        g_featsP[j] = v;
    }
}

// ---------------- conv kernels ----------------
__global__ void __launch_bounds__(224) k_stem1(const float* __restrict__ w,
                                               const float* __restrict__ bias)
{
    int b = blockIdx.y, ocg = blockIdx.x;
    float acc[2][2][8];
    conv_core(g_featsP + (size_t)b*1024*PCH, nullptr, 1024/CHUNK, w, 9216, ocg, acc);
    store_out(g_h1 + (size_t)b*PCN, nullptr, bias, ocg, acc);
}

__global__ void __launch_bounds__(224) k_stem2(const float* __restrict__ w,
                                               const float* __restrict__ bias)
{
    int b = blockIdx.y, ocg = blockIdx.x;
    float acc[2][2][8];
    conv_core(g_h1 + (size_t)b*PCN, nullptr, NC/CHUNK, w, 1152, ocg, acc);
    store_out(g_feat + (size_t)b*PCN, g_out + (size_t)b*PCN, bias, ocg, acc);
}

__global__ void __launch_bounds__(224) k_stage1(const int* __restrict__ programs,
                                                const float* __restrict__ mem_u,
                                                const float* __restrict__ mem_b, int step)
{
    int b = blockIdx.y, ocg = blockIdx.x;
    int tok = programs[b*NT + (NT-1-step)];
    int kind = c_kind[tok];
    if (kind == 0) return;
    const float* inA; const float* inB = nullptr; const float* w;
    int nchunk = NC/CHUNK, wstride = 1152;
    if (kind == 3) {
        inA = g_out + (size_t)b*PCN; inB = g_saved + (size_t)b*PCN;
        w = mem_b + (size_t)c_bidx[tok]*4*CONV_DIM;
        nchunk = 2*NC/CHUNK; wstride = 2304;
    } else {
        inA = (kind == 1 ? g_feat : g_out) + (size_t)b*PCN;
        w = mem_u + (size_t)c_uidx[tok]*2*CONV_DIM;
    }
    float acc[2][2][8];
    conv_core(inA, inB, nchunk, w, wstride, ocg, acc);
    store_out(g_tmp1 + (size_t)b*PCN, nullptr, nullptr, ocg, acc);
    // scene: new_saved = old out (copy this block's 32-channel slice)
    if (kind == 1) {
        size_t base = (size_t)b*PCN + (size_t)ocg*32*PCH;
        for (int i = threadIdx.x; i < 32*PCH; i += 224)
            g_saved[base + i] = g_out[base + i];
    }
}

__global__ void __launch_bounds__(224) k_stage2(const int* __restrict__ programs,
                                                const float* __restrict__ mem_u,
                                                const float* __restrict__ mem_b, int step)
{
    int b = blockIdx.y, ocg = blockIdx.x;
    int tok = programs[b*NT + (NT-1-step)];
    int kind = c_kind[tok];
    if (kind == 0) return;
    const float* w; float* out;
    if (kind == 3) {
        w = mem_b + (size_t)c_bidx[tok]*4*CONV_DIM + 2*CONV_DIM;
        out = g_tmp2;
    } else {
        w = mem_u + (size_t)c_uidx[tok]*2*CONV_DIM + CONV_DIM;
        out = g_out;
    }
    float acc[2][2][8];
    conv_core(g_tmp1 + (size_t)b*PCN, nullptr, NC/CHUNK, w, 1152, ocg, acc);
    store_out(out + (size_t)b*PCN, nullptr, nullptr, ocg, acc);
}

__global__ void __launch_bounds__(224) k_stage3(const int* __restrict__ programs,
                                                const float* __restrict__ mem_b, int step)
{
    int b = blockIdx.y, ocg = blockIdx.x;
    int tok = programs[b*NT + (NT-1-step)];
    if (c_kind[tok] != 3) return;
    const float* w = mem_b + (size_t)c_bidx[tok]*4*CONV_DIM + 3*CONV_DIM;
    float acc[2][2][8];
    conv_core(g_tmp2 + (size_t)b*PCN, nullptr, NC/CHUNK, w, 1152, ocg, acc);
    store_out(g_out + (size_t)b*PCN, nullptr, nullptr, ocg, acc);
}

// ---------------- classifier head ----------------
__global__ void k_cls(const float* __restrict__ w, const float* __restrict__ bias)
{
    __shared__ float s_in[32][NPIX];
    __shared__ float s_w[32][16];
    int b = blockIdx.y, ocg = blockIdx.x;
    int tid = threadIdx.x;
    float acc[16];
#pragma unroll
    for (int i=0;i<16;++i) acc[i]=0.f;
    for (int ch=0; ch<4; ++ch) {
        for (int idx=tid; idx<32*NPIX; idx+=256) {
            int ci = idx/NPIX, p = idx - ci*NPIX;
            int pi = (p/14 + 1)*16 + (p - 14*(p/14)) + 1;
            s_in[ci][p] = g_out[(size_t)b*PCN + (ch*32+ci)*PCH + pi];
        }
        for (int idx=tid; idx<32*16; idx+=256) {
            int ci = idx >> 4, oc = idx & 15;
            s_w[ci][oc] = w[(ocg*16+oc)*NC + ch*32 + ci];
        }
        __syncthreads();
        if (tid < NPIX) {
#pragma unroll 4
            for (int ci=0; ci<32; ++ci) {
                float v = s_in[ci][tid];
#pragma unroll
                for (int oc=0; oc<16; ++oc) acc[oc] += v*s_w[ci][oc];
            }
        }
        __syncthreads();
    }
    if (tid < NPIX) {
#pragma unroll
        for (int oc=0; oc<16; ++oc) {
            float r = acc[oc] + bias[ocg*16+oc];
            g_cls[((size_t)b*512 + ocg*16 + oc)*NPIX + tid] = r > 0.f ? r : 0.f;
        }
    }
}

__global__ void k_pool()
{
    int idx = blockIdx.x*blockDim.x + threadIdx.x;
    if (idx >= NB*512*49) return;
    int px = idx % 7;
    int r = idx / 7;
    int py = r % 7; r /= 7;
    int c = r % 512;
    int b = r / 512;
    const float* src = g_cls + (((size_t)b*512 + c)*NPIX) + (2*py)*HW + 2*px;
    float m = fmaxf(fmaxf(src[0], src[1]), fmaxf(src[HW], src[HW+1]));
    g_pool[idx] = m;
}

__global__ void k_fc1(const float* __restrict__ w)
{
    __shared__ float s_x[32][64];
    __shared__ float s_w[64][65];
    int oc0 = blockIdx.x*64;
    int k0  = blockIdx.y*3136;
    int tid = threadIdx.x;
    int oc_t = tid & 63;
    int bq = tid >> 6;
    float acc[8];
#pragma unroll
    for (int j=0;j<8;++j) acc[j]=0.f;
    for (int ch=0; ch<49; ++ch) {
        int kk0 = k0 + ch*64;
        for (int idx=tid; idx<2048; idx+=256) {
            int b = idx >> 6, kk = idx & 63;
            s_x[b][kk] = g_pool[b*25088 + kk0 + kk];
        }
        for (int idx=tid; idx<4096; idx+=256) {
            int oc = idx >> 6, kk = idx & 63;
            s_w[oc][kk] = w[(size_t)(oc0+oc)*25088 + kk0 + kk];
        }
        __syncthreads();
#pragma unroll 4
        for (int kk=0; kk<64; ++kk) {
            float wv = s_w[oc_t][kk];
#pragma unroll
            for (int j=0;j<8;++j) acc[j] += wv*s_x[bq*8+j][kk];
        }
        __syncthreads();
    }
#pragma unroll
    for (int j=0;j<8;++j) {
        int b = bq*8+j;
        g_fc1p[(size_t)blockIdx.y*NB*1024 + b*1024 + oc0 + oc_t] = acc[j];
    }
}

__global__ void k_fc2(const float* __restrict__ w2, const float* __restrict__ b2,
                      const float* __restrict__ fc1_b, float* __restrict__ out)
{
    __shared__ float s_x[1024];
    __shared__ float s_red[8][32];
    int b = blockIdx.x, tid = threadIdx.x;
    for (int j=tid; j<1024; j+=256) {
        float s = fc1_b[j];
        for (int ks=0; ks<8; ++ks)
            s += g_fc1p[(size_t)ks*NB*1024 + b*1024 + j];
        s_x[j] = s > 0.f ? s : 0.f;
    }
    __syncthreads();
    int a = tid & 31, part = tid >> 5;
    float acc = 0.f;
    int j0 = part*128;
    for (int j=j0; j<j0+128; ++j) acc += s_x[j]*w2[a*1024 + j];
    s_red[part][a] = acc;
    __syncthreads();
    if (tid < 32) {
        float s = b2[tid];
#pragma unroll
        for (int p=0;p<8;++p) s += s_red[p][tid];
        out[b*32 + tid] = s;
    }
}

// ---------------- launch ----------------
extern "C" void kernel_launch(void* const* d_in, const int* in_sizes, int n_in,
                              void* d_out, int out_size)
{
    const float* feats    = (const float*)d_in[0];
    const int*   programs = (const int*)  d_in[1];
    const float* stem_w1  = (const float*)d_in[2];
    const float* stem_b1  = (const float*)d_in[3];
    const float* stem_w2  = (const float*)d_in[4];
    const float* stem_b2  = (const float*)d_in[5];
    const float* mem_u    = (const float*)d_in[6];
    const float* mem_b    = (const float*)d_in[7];
    const float* cls_w    = (const float*)d_in[8];
    const float* cls_b    = (const float*)d_in[9];
    const float* fc1_w    = (const float*)d_in[10];
    const float* fc1_b    = (const float*)d_in[11];
    const float* fc2_w    = (const float*)d_in[12];
    const float* fc2_b    = (const float*)d_in[13];
    float* out = (float*)d_out;

    k_clear<<<2048, 256>>>();
    k_pad<<<8192, 256>>>(feats);

    dim3 gc(4, NB);
    k_stem1<<<gc, 224>>>(stem_w1, stem_b1);
    k_stem2<<<gc, 224>>>(stem_w2, stem_b2);
    for (int s = 0; s < NT; ++s) {
        k_stage1<<<gc, 224>>>(programs, mem_u, mem_b, s);
        k_stage2<<<gc, 224>>>(programs, mem_u, mem_b, s);
        k_stage3<<<gc, 224>>>(programs, mem_b, s);
    }
    k_cls<<<dim3(32, NB), 256>>>(cls_w, cls_b);
    k_pool<<<(NB*512*49 + 255)/256, 256>>>();
    k_fc1<<<dim3(16, 8), 256>>>(fc1_w);
    k_fc2<<<NB, 256>>>(fc2_w, fc2_b, fc1_b, out);
}

// round 4
// speedup vs baseline: 1.7829x; 1.4829x over previous
#include <cuda_runtime.h>

// ---------------- problem constants ----------------
#define NB 32
#define NT 30
#define NC 128
#define HW 14
#define NPIX 196
#define PCH 256            // padded 16x16 per channel
#define PCN (NC*PCH)       // 32768 floats per (b, 128ch) padded tensor
#define CONV_DIM (128*128*9)
#define CHUNK 8            // input channels per smem chunk
#define OCPB 16            // out channels per block
#define NOCG 8             // 128/OCPB

// token tables
__constant__ int c_kind[44] = {
  0,0,0,0, 1, 3,3,3,3,3,
  2,2,2,2,2,2,2,2,2,2,2,2,2,2,2,2,
  3,3,3,
  2,2,2,2,2,2,2,2,2,2,2,2,2,
  3, 2};
__constant__ int c_uidx[44] = {
  0,0,0,0, 0, 0,0,0,0,0,
  1,2,3,4,5,6,7,8,9,10,11,12,13,14,15,16,
  0,0,0,
  17,18,19,20,21,22,23,24,25,26,27,28,29,
  0, 30};
__constant__ int c_bidx[44] = {
  0,0,0,0, 0, 0,1,2,3,4,
  0,0,0,0,0,0,0,0,0,0,0,0,0,0,0,0,
  5,6,7,
  0,0,0,0,0,0,0,0,0,0,0,0,0,
  8, 0};

// ---------------- device scratch (padded layouts) ----------------
__device__ float g_featsP[NB*1024*PCH];
__device__ float g_h1[NB*PCN];
__device__ float g_feat[NB*PCN];
__device__ float g_out[NB*PCN];
__device__ float g_saved[NB*PCN];
__device__ float g_tmp1[NB*PCN];
__device__ float g_tmp2[NB*PCN];
__device__ float g_cls[NB*512*NPIX];
__device__ float g_pool[NB*512*49];
__device__ float g_fc1p[8*NB*1024];

// ---------------- cp.async helpers ----------------
__device__ __forceinline__ void cp_async16(void* smem_dst, const void* gsrc) {
    unsigned s = (unsigned)__cvta_generic_to_shared(smem_dst);
    asm volatile("cp.async.cg.shared.global [%0], [%1], 16;\n" :: "r"(s), "l"(gsrc));
}
__device__ __forceinline__ void cp_commit() { asm volatile("cp.async.commit_group;\n"); }
__device__ __forceinline__ void cp_wait0()  { asm volatile("cp.async.wait_group 0;\n"); }

// ---------------- conv core ----------------
// Block: 224 threads. ocs = tid/56 (0..3 -> 4 oc each), qid = tid%56 (2x2 quad).
// Thread computes 2x2 output pixels for 4 out channels (oc = ocg*16 + ocs*4 + k).
// Inputs padded [ch][16x16], zero borders.
__device__ __forceinline__ void conv_core(
    const float* __restrict__ inA, const float* __restrict__ inB,
    int nchunk, const float* __restrict__ w, int wstride,
    int ocg, float acc[2][2][4])
{
    __shared__ __align__(16) float s_in[2][CHUNK*PCH + 72];
    __shared__ __align__(16) float s_w[2][CHUNK*9][20];    // [ci*9+t][oc], pad 20
    const int tid = threadIdx.x;
    const int ocs = tid / 56;
    const int qid = tid - ocs*56;
    const int qy = qid >> 3, qx = qid & 7;
    const int p0 = qy*32 + qx*2;
    const int ocbase = ocg*OCPB;
    const int WCNT = OCPB*CHUNK*9;   // 1152 weight floats per chunk

#pragma unroll
    for (int r=0;r<2;++r)
#pragma unroll
    for (int c=0;c<2;++c)
#pragma unroll
    for (int k=0;k<4;++k) acc[r][c][k]=0.f;

    float wreg[6];

    // ---- prologue: chunk 0 ----
    for (int idx=tid; idx<CHUNK*PCH/4; idx+=224)
        cp_async16(&s_in[0][idx*4], (const float*)inA + idx*4);
    cp_commit();
    {
        int n=0;
        for (int idx=tid; idx<WCNT; idx+=224) {
            int oc = idx/(CHUNK*9), r = idx - oc*(CHUNK*9);
            wreg[n++] = w[(size_t)(ocbase+oc)*wstride + r];
        }
        cp_wait0(); __syncthreads();
        n=0;
        for (int idx=tid; idx<WCNT; idx+=224) {
            int oc = idx/(CHUNK*9), r = idx - oc*(CHUNK*9);
            s_w[0][r][oc] = wreg[n++];
        }
        __syncthreads();
    }

    for (int nc=0; nc<nchunk; ++nc) {
        const int nb = nc & 1;
        // prefetch chunk nc+1
        int n=0;
        if (nc+1 < nchunk) {
            const int cg0 = (nc+1)*CHUNK;
            const float* src = (inB != nullptr && cg0 >= NC) ? inB + (cg0-NC)*PCH
                                                             : inA + cg0*PCH;
            for (int idx=tid; idx<CHUNK*PCH/4; idx+=224)
                cp_async16(&s_in[nb^1][idx*4], src + idx*4);
            cp_commit();
            const int wbase = cg0*9;
            for (int idx=tid; idx<WCNT; idx+=224) {
                int oc = idx/(CHUNK*9), r = idx - oc*(CHUNK*9);
                wreg[n++] = w[(size_t)(ocbase+oc)*wstride + wbase + r];
            }
        }
        // compute chunk nc
        const float* sf = s_in[nb];
#pragma unroll 2
        for (int ci=0; ci<CHUNK; ++ci) {
            const float* bp = sf + ci*PCH + p0;
            float p[4][4];
#pragma unroll
            for (int rr=0; rr<4; ++rr) {
                float2 a = *(const float2*)(bp + rr*16);
                float2 b = *(const float2*)(bp + rr*16 + 2);
                p[rr][0]=a.x; p[rr][1]=a.y; p[rr][2]=b.x; p[rr][3]=b.y;
            }
#pragma unroll
            for (int t=0; t<9; ++t) {
                float4 w0 = *(const float4*)&s_w[nb][ci*9+t][ocs*4];
                float wv[4] = {w0.x,w0.y,w0.z,w0.w};
                const int ty=t/3, tx=t-3*(t/3);
#pragma unroll
                for (int r=0;r<2;++r)
#pragma unroll
                for (int c=0;c<2;++c) {
                    float pv = p[r+ty][c+tx];
#pragma unroll
                    for (int k=0;k<4;++k) acc[r][c][k] += pv*wv[k];
                }
            }
        }
        cp_wait0();
        __syncthreads();
        if (nc+1 < nchunk) {
            n=0;
            for (int idx=tid; idx<WCNT; idx+=224) {
                int oc = idx/(CHUNK*9), r = idx - oc*(CHUNK*9);
                s_w[nb^1][r][oc] = wreg[n++];
            }
        }
        __syncthreads();
    }
}

// epilogue: bias(optional) + relu, store to padded dst (and optional dst2)
__device__ __forceinline__ void store_out(
    float* __restrict__ dst, float* __restrict__ dst2,
    const float* __restrict__ bias, int ocg, float acc[2][2][4])
{
    const int tid = threadIdx.x;
    const int ocs = tid / 56;
    const int qid = tid - ocs*56;
    const int qy = qid >> 3, qx = qid & 7;
    if (qx == 7) return;
#pragma unroll
    for (int r=0;r<2;++r)
#pragma unroll
    for (int c=0;c<2;++c) {
        const int y = 2*qy+r, x = 2*qx+c;
        const int pi = (y+1)*16 + (x+1);
#pragma unroll
        for (int k=0;k<4;++k) {
            const int oc = ocg*OCPB + ocs*4 + k;
            float v = acc[r][c][k];
            if (bias) v += bias[oc];
            v = v > 0.f ? v : 0.f;
            dst[oc*PCH + pi] = v;
            if (dst2) dst2[oc*PCH + pi] = v;
        }
    }
}

// ---------------- init kernels ----------------
__global__ void k_clear()
{
    size_t i = (size_t)blockIdx.x*blockDim.x + threadIdx.x;
    const size_t n = (size_t)NB*PCN;
    for (size_t j = i; j < n; j += (size_t)gridDim.x*blockDim.x) {
        g_h1[j]=0.f; g_feat[j]=0.f; g_out[j]=0.f;
        g_saved[j]=0.f; g_tmp1[j]=0.f; g_tmp2[j]=0.f;
    }
}
__global__ void k_pad(const float* __restrict__ feats)
{
    size_t i = (size_t)blockIdx.x*blockDim.x + threadIdx.x;
    const size_t n = (size_t)NB*1024*PCH;
    for (size_t j = i; j < n; j += (size_t)gridDim.x*blockDim.x) {
        int px = j & 15, py = (j >> 4) & 15;
        size_t bc = j >> 8;
        float v = 0.f;
        if (px >= 1 && px <= 14 && py >= 1 && py <= 14)
            v = feats[bc*NPIX + (py-1)*14 + (px-1)];
        g_featsP[j] = v;
    }
}

// ---------------- conv kernels ----------------
__global__ void __launch_bounds__(224) k_stem1(const float* __restrict__ w,
                                               const float* __restrict__ bias)
{
    int b = blockIdx.y, ocg = blockIdx.x;
    float acc[2][2][4];
    conv_core(g_featsP + (size_t)b*1024*PCH, nullptr, 1024/CHUNK, w, 9216, ocg, acc);
    store_out(g_h1 + (size_t)b*PCN, nullptr, bias, ocg, acc);
}

__global__ void __launch_bounds__(224) k_stem2(const float* __restrict__ w,
                                               const float* __restrict__ bias)
{
    int b = blockIdx.y, ocg = blockIdx.x;
    float acc[2][2][4];
    conv_core(g_h1 + (size_t)b*PCN, nullptr, NC/CHUNK, w, 1152, ocg, acc);
    store_out(g_feat + (size_t)b*PCN, g_out + (size_t)b*PCN, bias, ocg, acc);
}

__global__ void __launch_bounds__(224) k_stage1(const int* __restrict__ programs,
                                                const float* __restrict__ mem_u,
                                                const float* __restrict__ mem_b, int step)
{
    int b = blockIdx.y, ocg = blockIdx.x;
    int tok = programs[b*NT + (NT-1-step)];
    int kind = c_kind[tok];
    if (kind == 0) return;
    const float* inA; const float* inB = nullptr; const float* w;
    int nchunk = NC/CHUNK, wstride = 1152;
    if (kind == 3) {
        inA = g_out + (size_t)b*PCN; inB = g_saved + (size_t)b*PCN;
        w = mem_b + (size_t)c_bidx[tok]*4*CONV_DIM;
        nchunk = 2*NC/CHUNK; wstride = 2304;
    } else {
        inA = (kind == 1 ? g_feat : g_out) + (size_t)b*PCN;
        w = mem_u + (size_t)c_uidx[tok]*2*CONV_DIM;
    }
    float acc[2][2][4];
    conv_core(inA, inB, nchunk, w, wstride, ocg, acc);
    store_out(g_tmp1 + (size_t)b*PCN, nullptr, nullptr, ocg, acc);
    if (kind == 1) {
        size_t base = (size_t)b*PCN + (size_t)ocg*OCPB*PCH;
        for (int i = threadIdx.x; i < OCPB*PCH; i += 224)
            g_saved[base + i] = g_out[base + i];
    }
}

__global__ void __launch_bounds__(224) k_stage2(const int* __restrict__ programs,
                                                const float* __restrict__ mem_u,
                                                const float* __restrict__ mem_b, int step)
{
    int b = blockIdx.y, ocg = blockIdx.x;
    int tok = programs[b*NT + (NT-1-step)];
    int kind = c_kind[tok];
    if (kind == 0) return;
    const float* w; float* out;
    if (kind == 3) {
        w = mem_b + (size_t)c_bidx[tok]*4*CONV_DIM + 2*CONV_DIM;
        out = g_tmp2;
    } else {
        w = mem_u + (size_t)c_uidx[tok]*2*CONV_DIM + CONV_DIM;
        out = g_out;
    }
    float acc[2][2][4];
    conv_core(g_tmp1 + (size_t)b*PCN, nullptr, NC/CHUNK, w, 1152, ocg, acc);
    store_out(out + (size_t)b*PCN, nullptr, nullptr, ocg, acc);
}

__global__ void __launch_bounds__(224) k_stage3(const int* __restrict__ programs,
                                                const float* __restrict__ mem_b, int step)
{
    int b = blockIdx.y, ocg = blockIdx.x;
    int tok = programs[b*NT + (NT-1-step)];
    if (c_kind[tok] != 3) return;
    const float* w = mem_b + (size_t)c_bidx[tok]*4*CONV_DIM + 3*CONV_DIM;
    float acc[2][2][4];
    conv_core(g_tmp2 + (size_t)b*PCN, nullptr, NC/CHUNK, w, 1152, ocg, acc);
    store_out(g_out + (size_t)b*PCN, nullptr, nullptr, ocg, acc);
}

// ---------------- classifier head ----------------
__global__ void k_cls(const float* __restrict__ w, const float* __restrict__ bias)
{
    __shared__ float s_in[32][NPIX];
    __shared__ float s_w[32][16];
    int b = blockIdx.y, ocg = blockIdx.x;
    int tid = threadIdx.x;
    float acc[16];
#pragma unroll
    for (int i=0;i<16;++i) acc[i]=0.f;
    for (int ch=0; ch<4; ++ch) {
        for (int idx=tid; idx<32*NPIX; idx+=256) {
            int ci = idx/NPIX, p = idx - ci*NPIX;
            int pi = (p/14 + 1)*16 + (p - 14*(p/14)) + 1;
            s_in[ci][p] = g_out[(size_t)b*PCN + (ch*32+ci)*PCH + pi];
        }
        for (int idx=tid; idx<32*16; idx+=256) {
            int ci = idx >> 4, oc = idx & 15;
            s_w[ci][oc] = w[(ocg*16+oc)*NC + ch*32 + ci];
        }
        __syncthreads();
        if (tid < NPIX) {
#pragma unroll 4
            for (int ci=0; ci<32; ++ci) {
                float v = s_in[ci][tid];
#pragma unroll
                for (int oc=0; oc<16; ++oc) acc[oc] += v*s_w[ci][oc];
            }
        }
        __syncthreads();
    }
    if (tid < NPIX) {
#pragma unroll
        for (int oc=0; oc<16; ++oc) {
            float r = acc[oc] + bias[ocg*16+oc];
            g_cls[((size_t)b*512 + ocg*16 + oc)*NPIX + tid] = r > 0.f ? r : 0.f;
        }
    }
}

__global__ void k_pool()
{
    int idx = blockIdx.x*blockDim.x + threadIdx.x;
    if (idx >= NB*512*49) return;
    int px = idx % 7;
    int r = idx / 7;
    int py = r % 7; r /= 7;
    int c = r % 512;
    int b = r / 512;
    const float* src = g_cls + (((size_t)b*512 + c)*NPIX) + (2*py)*HW + 2*px;
    float m = fmaxf(fmaxf(src[0], src[1]), fmaxf(src[HW], src[HW+1]));
    g_pool[idx] = m;
}

__global__ void k_fc1(const float* __restrict__ w)
{
    __shared__ float s_x[32][64];
    __shared__ float s_w[64][65];
    int oc0 = blockIdx.x*64;
    int k0  = blockIdx.y*3136;
    int tid = threadIdx.x;
    int oc_t = tid & 63;
    int bq = tid >> 6;
    float acc[8];
#pragma unroll
    for (int j=0;j<8;++j) acc[j]=0.f;
    for (int ch=0; ch<49; ++ch) {
        int kk0 = k0 + ch*64;
        for (int idx=tid; idx<2048; idx+=256) {
            int b = idx >> 6, kk = idx & 63;
            s_x[b][kk] = g_pool[b*25088 + kk0 + kk];
        }
        for (int idx=tid; idx<4096; idx+=256) {
            int oc = idx >> 6, kk = idx & 63;
            s_w[oc][kk] = w[(size_t)(oc0+oc)*25088 + kk0 + kk];
        }
        __syncthreads();
#pragma unroll 4
        for (int kk=0; kk<64; ++kk) {
            float wv = s_w[oc_t][kk];
#pragma unroll
            for (int j=0;j<8;++j) acc[j] += wv*s_x[bq*8+j][kk];
        }
        __syncthreads();
    }
#pragma unroll
    for (int j=0;j<8;++j) {
        int b = bq*8+j;
        g_fc1p[(size_t)blockIdx.y*NB*1024 + b*1024 + oc0 + oc_t] = acc[j];
    }
}

__global__ void k_fc2(const float* __restrict__ w2, const float* __restrict__ b2,
                      const float* __restrict__ fc1_b, float* __restrict__ out)
{
    __shared__ float s_x[1024];
    __shared__ float s_red[8][32];
    int b = blockIdx.x, tid = threadIdx.x;
    for (int j=tid; j<1024; j+=256) {
        float s = fc1_b[j];
        for (int ks=0; ks<8; ++ks)
            s += g_fc1p[(size_t)ks*NB*1024 + b*1024 + j];
        s_x[j] = s > 0.f ? s : 0.f;
    }
    __syncthreads();
    int a = tid & 31, part = tid >> 5;
    float acc = 0.f;
    int j0 = part*128;
    for (int j=j0; j<j0+128; ++j) acc += s_x[j]*w2[a*1024 + j];
    s_red[part][a] = acc;
    __syncthreads();
    if (tid < 32) {
        float s = b2[tid];
#pragma unroll
        for (int p=0;p<8;++p) s += s_red[p][tid];
        out[b*32 + tid] = s;
    }
}

// ---------------- launch ----------------
extern "C" void kernel_launch(void* const* d_in, const int* in_sizes, int n_in,
                              void* d_out, int out_size)
{
    const float* feats    = (const float*)d_in[0];
    const int*   programs = (const int*)  d_in[1];
    const float* stem_w1  = (const float*)d_in[2];
    const float* stem_b1  = (const float*)d_in[3];
    const float* stem_w2  = (const float*)d_in[4];
    const float* stem_b2  = (const float*)d_in[5];
    const float* mem_u    = (const float*)d_in[6];
    const float* mem_b    = (const float*)d_in[7];
    const float* cls_w    = (const float*)d_in[8];
    const float* cls_b    = (const float*)d_in[9];
    const float* fc1_w    = (const float*)d_in[10];
    const float* fc1_b    = (const float*)d_in[11];
    const float* fc2_w    = (const float*)d_in[12];
    const float* fc2_b    = (const float*)d_in[13];
    float* out = (float*)d_out;

    k_clear<<<2048, 256>>>();
    k_pad<<<8192, 256>>>(feats);

    dim3 gc(NOCG, NB);   // 8 x 32 = 256 blocks
    k_stem1<<<gc, 224>>>(stem_w1, stem_b1);
    k_stem2<<<gc, 224>>>(stem_w2, stem_b2);
    for (int s = 0; s < NT; ++s) {
        k_stage1<<<gc, 224>>>(programs, mem_u, mem_b, s);
        k_stage2<<<gc, 224>>>(programs, mem_u, mem_b, s);
        k_stage3<<<gc, 224>>>(programs, mem_b, s);
    }
    k_cls<<<dim3(32, NB), 256>>>(cls_w, cls_b);
    k_pool<<<(NB*512*49 + 255)/256, 256>>>();
    k_fc1<<<dim3(16, 8), 256>>>(fc1_w);
    k_fc2<<<NB, 256>>>(fc2_w, fc2_b, fc1_b, out);
}